// round 4
// baseline (speedup 1.0000x reference)
#include <cuda_runtime.h>
#include <cuda_bf16.h>
#include <cstdint>

// ---------------------------------------------------------------------------
// MPEdgeNodeBlock — warp-level tensor-core version (mma.sync bf16 + hi/lo
// split, fp32 accum).  tcgen05 is unavailable: harness PTX targets sm_103
// (no 'a' feature set), so we use arch-generic HMMA.
// ---------------------------------------------------------------------------
#define N_NODES 25000
#define N_EDGES 200000
#define IN_F    64
#define OUT_F   64
#define HDIM    192

// -------------------- scratch (device globals; no runtime alloc) ------------
__device__ float g_Xr[N_NODES * HDIM];
__device__ float g_Xi[N_NODES * HDIM];
__device__ float g_Xt[N_NODES * HDIM];
__device__ float g_Yr[(size_t)N_EDGES * HDIM];
__device__ float g_Yi[(size_t)N_EDGES * HDIM];
__device__ float g_Yt[(size_t)N_EDGES * HDIM];
__device__ int   g_row[N_EDGES];
__device__ int   g_col[N_EDGES];
__device__ int   g_is64;

// split weights: hi/lo bf16 copies of all weight matrices
#define W_TOTAL 253952
__device__ __nv_bfloat16 g_Whi[W_TOTAL];
__device__ __nv_bfloat16 g_Wlo[W_TOTAL];
// offsets (elements)
#define OFF_WN   0
#define OFF_WE   4096
#define OFF_NW   8192       // node_W  3*192*192 = 110592
#define OFF_NOW  118784     // node_oW 64*192    = 12288
#define OFF_EW   131072     // edge_W  110592
#define OFF_EOW  241664     // edge_oW 12288

// -------------------- small helpers -----------------------------------------
__device__ __forceinline__ uint32_t smem_u32(const void* p) {
    uint32_t a;
    asm("{ .reg .u64 t; cvta.to.shared.u64 t, %1; cvt.u32.u64 %0, t; }"
        : "=r"(a) : "l"(p));
    return a;
}

__device__ __forceinline__ void ldsm_x4(uint32_t& r0, uint32_t& r1,
                                        uint32_t& r2, uint32_t& r3,
                                        uint32_t addr) {
    asm volatile("ldmatrix.sync.aligned.m8n8.x4.shared.b16 {%0,%1,%2,%3}, [%4];"
                 : "=r"(r0), "=r"(r1), "=r"(r2), "=r"(r3) : "r"(addr));
}

__device__ __forceinline__ void mma_bf16(float* c, const uint32_t* a,
                                         const uint32_t* b) {
    asm volatile(
        "mma.sync.aligned.m16n8k16.row.col.f32.bf16.bf16.f32 "
        "{%0,%1,%2,%3}, {%4,%5,%6,%7}, {%8,%9}, {%0,%1,%2,%3};"
        : "+f"(c[0]), "+f"(c[1]), "+f"(c[2]), "+f"(c[3])
        : "r"(a[0]), "r"(a[1]), "r"(a[2]), "r"(a[3]), "r"(b[0]), "r"(b[1]));
}

// -------------------- edge_index dtype detection + conversion ---------------
__global__ void k_detect(const unsigned int* __restrict__ p) {
    if (threadIdx.x == 0) {
        int all_zero = 1;
        for (int i = 0; i < 128; ++i)
            if (p[2 * i + 1] != 0u) { all_zero = 0; break; }
        g_is64 = all_zero;
    }
}

__global__ void k_convert(const void* __restrict__ raw) {
    int e = blockIdx.x * blockDim.x + threadIdx.x;
    if (e >= N_EDGES) return;
    if (g_is64) {
        const long long* p = (const long long*)raw;
        g_row[e] = (int)p[2 * e];
        g_col[e] = (int)p[2 * e + 1];
    } else {
        const int* p = (const int*)raw;
        g_row[e] = p[2 * e];
        g_col[e] = p[2 * e + 1];
    }
}

__global__ void k_zeroX() {
    int i = blockIdx.x * blockDim.x + threadIdx.x;
    if (i < N_NODES * HDIM) { g_Xr[i] = 0.f; g_Xi[i] = 0.f; }
}

// -------------------- weight split: fp32 -> bf16 hi + bf16 lo ---------------
__global__ void k_splitw(const float* __restrict__ src, int n, int dstOff) {
    int i = blockIdx.x * blockDim.x + threadIdx.x;
    if (i >= n) return;
    float f = src[i];
    __nv_bfloat16 h = __float2bfloat16(f);
    __nv_bfloat16 l = __float2bfloat16(f - __bfloat162float(h));
    g_Whi[dstOff + i] = h;
    g_Wlo[dstOff + i] = l;
}

// -------------------- HMMA GEMM: C = act(A @ W^T + b) -----------------------
// A: M x K fp32 (row-major, lda).  W (split, bf16 hi/lo): Ntot x K.
// C: M x Ntot tile rows, ldc.  Block computes 128 rows, loops n in 64-chunks.
// 256 threads = 8 warps in 4(m) x 2(n) grid; warp tile 32x32.
__global__ __launch_bounds__(256)
void k_gemm_hmma(const float* __restrict__ A, int M, int K, int lda,
                 const __nv_bfloat16* __restrict__ Whi,
                 const __nv_bfloat16* __restrict__ Wlo, int Ntot,
                 const float* __restrict__ bias,
                 const float* __restrict__ alphaPtr,
                 float* __restrict__ C, int ldc)
{
    extern __shared__ __align__(128) char smem[];
    const int KPAD = K + 8;                       // conflict-free ldmatrix
    const uint32_t sb    = smem_u32(smem);
    const uint32_t aHi32 = sb;
    const uint32_t aLo32 = sb + (uint32_t)(128 * KPAD * 2);
    char* aHiP = smem;
    char* aLoP = smem + 128 * KPAD * 2;

    const int tid  = threadIdx.x;
    const int lane = tid & 31;
    const int wid  = tid >> 5;
    const int wm   = wid >> 1;                    // 0..3
    const int wn   = wid & 1;                     // 0..1
    const int bm   = blockIdx.x * 128;

    // ---- load + split A tile (128 x K) into smem hi/lo ----
    const int vpr = K >> 2;                       // float4 per row
    for (int idx = tid; idx < 128 * vpr; idx += 256) {
        int row = idx / vpr;
        int kq  = (idx - row * vpr) << 2;
        int gm  = bm + row;
        float4 v = make_float4(0.f, 0.f, 0.f, 0.f);
        if (gm < M)
            v = *reinterpret_cast<const float4*>(A + (size_t)gm * lda + kq);
        float f[4] = {v.x, v.y, v.z, v.w};
        uint32_t hw[2], lw[2];
#pragma unroll
        for (int j = 0; j < 2; ++j) {
            __nv_bfloat16 h0 = __float2bfloat16(f[2*j]);
            __nv_bfloat16 h1 = __float2bfloat16(f[2*j+1]);
            __nv_bfloat16 l0 = __float2bfloat16(f[2*j]   - __bfloat162float(h0));
            __nv_bfloat16 l1 = __float2bfloat16(f[2*j+1] - __bfloat162float(h1));
            hw[j] = (uint32_t)__bfloat16_as_ushort(h0) | ((uint32_t)__bfloat16_as_ushort(h1) << 16);
            lw[j] = (uint32_t)__bfloat16_as_ushort(l0) | ((uint32_t)__bfloat16_as_ushort(l1) << 16);
        }
        int off = (row * KPAD + kq) * 2;
        *reinterpret_cast<uint2*>(aHiP + off) = make_uint2(hw[0], hw[1]);
        *reinterpret_cast<uint2*>(aLoP + off) = make_uint2(lw[0], lw[1]);
    }
    __syncthreads();

    // ldmatrix per-lane address component (rows m, k-phase select)
    const int aRowOff = (wm * 32 + (lane & 15)) * KPAD + (lane >> 4) * 8;
    // B per-thread indexing
    const int bRow = wn * 32 + (lane >> 2);       // n within 64-chunk
    const int bK   = (lane & 3) * 2;

    const bool  act = (alphaPtr != nullptr);
    const float al  = act ? __ldg(alphaPtr) : 1.0f;
    const int   nks = K >> 4;

    for (int nb = 0; nb < Ntot; nb += 64) {
        float c[2][4][4];
#pragma unroll
        for (int i = 0; i < 2; ++i)
#pragma unroll
            for (int j = 0; j < 4; ++j)
#pragma unroll
                for (int q = 0; q < 4; ++q) c[i][j][q] = 0.f;

#pragma unroll
        for (int pass = 0; pass < 3; ++pass) {
            // pass0: A_hi*B_hi, pass1: A_hi*B_lo, pass2: A_lo*B_hi
            const __nv_bfloat16* Bp =
                ((pass == 1) ? Wlo : Whi) + (size_t)(nb + bRow) * K + bK;
            const uint32_t aBase = (pass == 2) ? aLo32 : aHi32;

            for (int ks = 0; ks < nks; ++ks) {
                uint32_t a0[4], a1[4];
                ldsm_x4(a0[0], a0[1], a0[2], a0[3],
                        aBase + (uint32_t)((aRowOff + ks * 16) * 2));
                ldsm_x4(a1[0], a1[1], a1[2], a1[3],
                        aBase + (uint32_t)((aRowOff + 16 * KPAD + ks * 16) * 2));
                uint32_t b[4][2];
#pragma unroll
                for (int f = 0; f < 4; ++f) {
                    b[f][0] = *reinterpret_cast<const uint32_t*>(Bp + f * 8 * K + ks * 16);
                    b[f][1] = *reinterpret_cast<const uint32_t*>(Bp + f * 8 * K + ks * 16 + 8);
                }
#pragma unroll
                for (int f = 0; f < 4; ++f) {
                    mma_bf16(c[0][f], a0, b[f]);
                    mma_bf16(c[1][f], a1, b[f]);
                }
            }
        }

        // ---- epilogue: bias + leaky-relu, float2 stores ----
#pragma unroll
        for (int f = 0; f < 4; ++f) {
            int col = nb + wn * 32 + f * 8 + (lane & 3) * 2;
            float bx = __ldg(bias + col);
            float by = __ldg(bias + col + 1);
#pragma unroll
            for (int mt = 0; mt < 2; ++mt) {
                int row0 = bm + wm * 32 + mt * 16 + (lane >> 2);
                float v0 = c[mt][f][0] + bx;
                float v1 = c[mt][f][1] + by;
                float v2 = c[mt][f][2] + bx;
                float v3 = c[mt][f][3] + by;
                if (act) {
                    v0 = (v0 >= 0.f) ? v0 : al * v0;
                    v1 = (v1 >= 0.f) ? v1 : al * v1;
                    v2 = (v2 >= 0.f) ? v2 : al * v2;
                    v3 = (v3 >= 0.f) ? v3 : al * v3;
                }
                if (row0 < M)
                    *reinterpret_cast<float2*>(C + (size_t)row0 * ldc + col) =
                        make_float2(v0, v1);
                if (row0 + 8 < M)
                    *reinterpret_cast<float2*>(C + (size_t)(row0 + 8) * ldc + col) =
                        make_float2(v2, v3);
            }
        }
    }
}

// -------------------- node aggregation (segment-sum via atomics) ------------
__global__ void k_scatter() {
    int t = blockIdx.x * blockDim.x + threadIdx.x;
    if (t >= N_EDGES * IN_F) return;
    int e = t >> 6;
    int f = t & 63;
    int r = g_row[e];
    int c = g_col[e];

    float vnr = g_Xr[(size_t)c * HDIM + f];
    float vni = g_Xi[(size_t)c * HDIM + f];
    float ver = g_Yr[(size_t)e * HDIM + f];
    float vei = g_Yi[(size_t)e * HDIM + f];

    atomicAdd(&g_Xr[(size_t)r * HDIM + 64  + f], vnr);
    atomicAdd(&g_Xr[(size_t)r * HDIM + 128 + f], ver);
    atomicAdd(&g_Xi[(size_t)r * HDIM + 64  + f], vni);
    atomicAdd(&g_Xi[(size_t)r * HDIM + 128 + f], vei);
}

// -------------------- edge gather -------------------------------------------
__global__ void k_gather(const float* __restrict__ hr,
                         const float* __restrict__ hi) {
    int t = blockIdx.x * blockDim.x + threadIdx.x;
    if (t >= N_EDGES * IN_F) return;
    int e = t >> 6;
    int f = t & 63;
    int r = g_row[e];
    int c = g_col[e];
    g_Yr[(size_t)e * HDIM + 64  + f] = hr[(size_t)r * OUT_F + f];
    g_Yr[(size_t)e * HDIM + 128 + f] = hr[(size_t)c * OUT_F + f];
    g_Yi[(size_t)e * HDIM + 64  + f] = hi[(size_t)r * OUT_F + f];
    g_Yi[(size_t)e * HDIM + 128 + f] = hi[(size_t)c * OUT_F + f];
}

// ---------------------------------------------------------------------------
static float* symaddr(const void* sym) {
    void* p = nullptr;
    cudaGetSymbolAddress(&p, sym);
    return (float*)p;
}

static __nv_bfloat16* symaddr_bf(const void* sym) {
    void* p = nullptr;
    cudaGetSymbolAddress(&p, sym);
    return (__nv_bfloat16*)p;
}

static inline void launch_gemm(const float* A, int M, int K, int lda,
                               const __nv_bfloat16* Whi, const __nv_bfloat16* Wlo,
                               int Ntot, const float* bias, const float* alpha,
                               float* C, int ldc) {
    dim3 grid((M + 127) / 128);
    int smemBytes = 2 * 128 * (K + 8) * 2;
    k_gemm_hmma<<<grid, 256, smemBytes>>>(A, M, K, lda, Whi, Wlo, Ntot,
                                          bias, alpha, C, ldc);
}

extern "C" void kernel_launch(void* const* d_in, const int* in_sizes, int n_in,
                              void* d_out, int out_size)
{
    const float* node_real = (const float*)d_in[0];
    const float* node_imag = (const float*)d_in[1];
    const float* edge_real = (const float*)d_in[2];
    const float* edge_imag = (const float*)d_in[3];
    const void*  edge_idx  = d_in[4];
    const float* Wn        = (const float*)d_in[5];
    const float* bn_       = (const float*)d_in[6];
    const float* We        = (const float*)d_in[7];
    const float* be_       = (const float*)d_in[8];
    const float* node_W    = (const float*)d_in[9];
    const float* node_b    = (const float*)d_in[10];
    const float* node_al   = (const float*)d_in[11];
    const float* node_oW   = (const float*)d_in[12];
    const float* node_ob   = (const float*)d_in[13];
    const float* edge_W    = (const float*)d_in[14];
    const float* edge_b    = (const float*)d_in[15];
    const float* edge_al   = (const float*)d_in[16];
    const float* edge_oW   = (const float*)d_in[17];
    const float* edge_ob   = (const float*)d_in[18];

    float* out  = (float*)d_out;
    float* hr   = out;
    float* hi   = out + (size_t)N_NODES * OUT_F;
    float* outr = out + 2 * (size_t)N_NODES * OUT_F;
    float* outi = outr + (size_t)N_EDGES * OUT_F;

    float* Xr = symaddr(g_Xr);
    float* Xi = symaddr(g_Xi);
    float* Xt = symaddr(g_Xt);
    float* Yr = symaddr(g_Yr);
    float* Yi = symaddr(g_Yi);
    float* Yt = symaddr(g_Yt);
    __nv_bfloat16* Whi = symaddr_bf(g_Whi);
    __nv_bfloat16* Wlo = symaddr_bf(g_Wlo);

    // allow 100KB dynamic smem for the K=192 tiles (idempotent host call)
    cudaFuncSetAttribute(k_gemm_hmma, cudaFuncAttributeMaxDynamicSharedMemorySize,
                         2 * 128 * (HDIM + 8) * 2);

    const int TPB = 256;

    // 1. edge index conversion
    k_detect<<<1, 32>>>((const unsigned int*)edge_idx);
    k_convert<<<(N_EDGES + TPB - 1) / TPB, TPB>>>(edge_idx);

    // 2. weight splits (fp32 -> bf16 hi/lo)
    k_splitw<<<(4096   + TPB - 1) / TPB, TPB>>>(Wn,      4096,   OFF_WN);
    k_splitw<<<(4096   + TPB - 1) / TPB, TPB>>>(We,      4096,   OFF_WE);
    k_splitw<<<(110592 + TPB - 1) / TPB, TPB>>>(node_W,  110592, OFF_NW);
    k_splitw<<<(12288  + TPB - 1) / TPB, TPB>>>(node_oW, 12288,  OFF_NOW);
    k_splitw<<<(110592 + TPB - 1) / TPB, TPB>>>(edge_W,  110592, OFF_EW);
    k_splitw<<<(12288  + TPB - 1) / TPB, TPB>>>(edge_oW, 12288,  OFF_EOW);

    // 3. zero node agg buffers
    k_zeroX<<<(N_NODES * HDIM + TPB - 1) / TPB, TPB>>>();

    // 4. projections: nr/ni -> X[:,0:64], er/ei -> Y[:,0:64]
    launch_gemm(node_real, N_NODES, IN_F, IN_F, Whi + OFF_WN, Wlo + OFF_WN, OUT_F, bn_, nullptr, Xr, HDIM);
    launch_gemm(node_imag, N_NODES, IN_F, IN_F, Whi + OFF_WN, Wlo + OFF_WN, OUT_F, bn_, nullptr, Xi, HDIM);
    launch_gemm(edge_real, N_EDGES, IN_F, IN_F, Whi + OFF_WE, Wlo + OFF_WE, OUT_F, be_, nullptr, Yr, HDIM);
    launch_gemm(edge_imag, N_EDGES, IN_F, IN_F, Whi + OFF_WE, Wlo + OFF_WE, OUT_F, be_, nullptr, Yi, HDIM);

    // 5. node aggregation
    k_scatter<<<(N_EDGES * IN_F + TPB - 1) / TPB, TPB>>>();

    const int HH = HDIM * HDIM;

    // 6. node MLP (real): Xr -> Xt -> Xr -> Xt -> hr
    launch_gemm(Xr, N_NODES, HDIM, HDIM, Whi + OFF_NW,          Wlo + OFF_NW,          HDIM, node_b,            node_al,     Xt, HDIM);
    launch_gemm(Xt, N_NODES, HDIM, HDIM, Whi + OFF_NW + HH,     Wlo + OFF_NW + HH,     HDIM, node_b + HDIM,     node_al + 1, Xr, HDIM);
    launch_gemm(Xr, N_NODES, HDIM, HDIM, Whi + OFF_NW + 2*HH,   Wlo + OFF_NW + 2*HH,   HDIM, node_b + 2*HDIM,   node_al + 2, Xt, HDIM);
    launch_gemm(Xt, N_NODES, HDIM, HDIM, Whi + OFF_NOW,         Wlo + OFF_NOW,         OUT_F, node_ob, nullptr, hr, OUT_F);

    //    node MLP (imag)
    launch_gemm(Xi, N_NODES, HDIM, HDIM, Whi + OFF_NW,          Wlo + OFF_NW,          HDIM, node_b,            node_al,     Xt, HDIM);
    launch_gemm(Xt, N_NODES, HDIM, HDIM, Whi + OFF_NW + HH,     Wlo + OFF_NW + HH,     HDIM, node_b + HDIM,     node_al + 1, Xi, HDIM);
    launch_gemm(Xi, N_NODES, HDIM, HDIM, Whi + OFF_NW + 2*HH,   Wlo + OFF_NW + 2*HH,   HDIM, node_b + 2*HDIM,   node_al + 2, Xt, HDIM);
    launch_gemm(Xt, N_NODES, HDIM, HDIM, Whi + OFF_NOW,         Wlo + OFF_NOW,         OUT_F, node_ob, nullptr, hi, OUT_F);

    // 7. edge gather (needs hr/hi from d_out)
    k_gather<<<(N_EDGES * IN_F + TPB - 1) / TPB, TPB>>>(hr, hi);

    // 8. edge MLP (real): Yr -> Yt -> Yr -> Yt -> outr
    launch_gemm(Yr, N_EDGES, HDIM, HDIM, Whi + OFF_EW,          Wlo + OFF_EW,          HDIM, edge_b,            edge_al,     Yt, HDIM);
    launch_gemm(Yt, N_EDGES, HDIM, HDIM, Whi + OFF_EW + HH,     Wlo + OFF_EW + HH,     HDIM, edge_b + HDIM,     edge_al + 1, Yr, HDIM);
    launch_gemm(Yr, N_EDGES, HDIM, HDIM, Whi + OFF_EW + 2*HH,   Wlo + OFF_EW + 2*HH,   HDIM, edge_b + 2*HDIM,   edge_al + 2, Yt, HDIM);
    launch_gemm(Yt, N_EDGES, HDIM, HDIM, Whi + OFF_EOW,         Wlo + OFF_EOW,         OUT_F, edge_ob, nullptr, outr, OUT_F);

    //    edge MLP (imag)
    launch_gemm(Yi, N_EDGES, HDIM, HDIM, Whi + OFF_EW,          Wlo + OFF_EW,          HDIM, edge_b,            edge_al,     Yt, HDIM);
    launch_gemm(Yt, N_EDGES, HDIM, HDIM, Whi + OFF_EW + HH,     Wlo + OFF_EW + HH,     HDIM, edge_b + HDIM,     edge_al + 1, Yi, HDIM);
    launch_gemm(Yi, N_EDGES, HDIM, HDIM, Whi + OFF_EW + 2*HH,   Wlo + OFF_EW + 2*HH,   HDIM, edge_b + 2*HDIM,   edge_al + 2, Yt, HDIM);
    launch_gemm(Yt, N_EDGES, HDIM, HDIM, Whi + OFF_EOW,         Wlo + OFF_EOW,         OUT_F, edge_ob, nullptr, outi, OUT_F);
}

// round 5
// speedup vs baseline: 1.4150x; 1.4150x over previous
#include <cuda_runtime.h>
#include <cuda_bf16.h>
#include <cstdint>

// ---------------------------------------------------------------------------
// MPEdgeNodeBlock — warp-level tensor-core version (mma.sync bf16 hi/lo split,
// fp32 accum).  R4: both A and B operands staged in smem and fed via ldmatrix
// (R3's per-thread global B loads were 8-way sector-fragmented -> 30us/block).
// ---------------------------------------------------------------------------
#define N_NODES 25000
#define N_EDGES 200000
#define IN_F    64
#define OUT_F   64
#define HDIM    192

// -------------------- scratch (device globals; no runtime alloc) ------------
__device__ float g_Xr[N_NODES * HDIM];
__device__ float g_Xi[N_NODES * HDIM];
__device__ float g_Xt[N_NODES * HDIM];
__device__ float g_Yr[(size_t)N_EDGES * HDIM];
__device__ float g_Yi[(size_t)N_EDGES * HDIM];
__device__ float g_Yt[(size_t)N_EDGES * HDIM];
__device__ int   g_row[N_EDGES];
__device__ int   g_col[N_EDGES];
__device__ int   g_is64;

// split weights: hi/lo bf16 copies of all weight matrices (16B aligned)
#define W_TOTAL 253952
__device__ __align__(256) __nv_bfloat16 g_Whi[W_TOTAL];
__device__ __align__(256) __nv_bfloat16 g_Wlo[W_TOTAL];
#define OFF_WN   0
#define OFF_WE   4096
#define OFF_NW   8192
#define OFF_NOW  118784
#define OFF_EW   131072
#define OFF_EOW  241664

// -------------------- small helpers -----------------------------------------
__device__ __forceinline__ uint32_t smem_u32(const void* p) {
    uint32_t a;
    asm("{ .reg .u64 t; cvta.to.shared.u64 t, %1; cvt.u32.u64 %0, t; }"
        : "=r"(a) : "l"(p));
    return a;
}

__device__ __forceinline__ void ldsm_x4(uint32_t& r0, uint32_t& r1,
                                        uint32_t& r2, uint32_t& r3,
                                        uint32_t addr) {
    asm volatile("ldmatrix.sync.aligned.m8n8.x4.shared.b16 {%0,%1,%2,%3}, [%4];"
                 : "=r"(r0), "=r"(r1), "=r"(r2), "=r"(r3) : "r"(addr));
}

__device__ __forceinline__ void mma_bf16(float* c, const uint32_t* a,
                                         const uint32_t* b) {
    asm volatile(
        "mma.sync.aligned.m16n8k16.row.col.f32.bf16.bf16.f32 "
        "{%0,%1,%2,%3}, {%4,%5,%6,%7}, {%8,%9}, {%0,%1,%2,%3};"
        : "+f"(c[0]), "+f"(c[1]), "+f"(c[2]), "+f"(c[3])
        : "r"(a[0]), "r"(a[1]), "r"(a[2]), "r"(a[3]), "r"(b[0]), "r"(b[1]));
}

// -------------------- edge_index dtype detection + conversion ---------------
__global__ void k_detect(const unsigned int* __restrict__ p) {
    if (threadIdx.x == 0) {
        int all_zero = 1;
        for (int i = 0; i < 128; ++i)
            if (p[2 * i + 1] != 0u) { all_zero = 0; break; }
        g_is64 = all_zero;
    }
}

__global__ void k_convert(const void* __restrict__ raw) {
    int e = blockIdx.x * blockDim.x + threadIdx.x;
    if (e >= N_EDGES) return;
    if (g_is64) {
        const long long* p = (const long long*)raw;
        g_row[e] = (int)p[2 * e];
        g_col[e] = (int)p[2 * e + 1];
    } else {
        const int* p = (const int*)raw;
        g_row[e] = p[2 * e];
        g_col[e] = p[2 * e + 1];
    }
}

__global__ void k_zeroX() {
    int i = blockIdx.x * blockDim.x + threadIdx.x;
    if (i < N_NODES * HDIM) { g_Xr[i] = 0.f; g_Xi[i] = 0.f; }
}

// -------------------- weight split: fp32 -> bf16 hi + bf16 lo ---------------
__global__ void k_splitw(const float* __restrict__ src, int n, int dstOff) {
    int i = blockIdx.x * blockDim.x + threadIdx.x;
    if (i >= n) return;
    float f = src[i];
    __nv_bfloat16 h = __float2bfloat16(f);
    __nv_bfloat16 l = __float2bfloat16(f - __bfloat162float(h));
    g_Whi[dstOff + i] = h;
    g_Wlo[dstOff + i] = l;
}

// -------------------- HMMA GEMM: C = act(A @ W^T + b) -----------------------
// A: M x K fp32 (row-major, lda).  W (split bf16 hi/lo): Ntot x K row-major.
// Block: 128 rows, loops n in 64-chunks.  256 thr = 8 warps, 4(m) x 2(n),
// warp tile 32x32.  A and B both in smem, ldmatrix-fed.  3 fused passes:
// hi*hi + hi*lo + lo*hi.
__global__ __launch_bounds__(256)
void k_gemm_hmma(const float* __restrict__ A, int M, int K, int lda,
                 const __nv_bfloat16* __restrict__ Whi,
                 const __nv_bfloat16* __restrict__ Wlo, int Ntot,
                 const float* __restrict__ bias,
                 const float* __restrict__ alphaPtr,
                 float* __restrict__ C, int ldc)
{
    extern __shared__ __align__(128) char smem[];
    const int KPAD = K + 8;
    const uint32_t rowB = (uint32_t)(KPAD * 2);       // smem row bytes
    char* aHiP = smem;
    char* aLoP = aHiP + 128 * KPAD * 2;
    char* bHiP = aLoP + 128 * KPAD * 2;
    char* bLoP = bHiP + 64 * KPAD * 2;
    const uint32_t aHi32 = smem_u32(aHiP);
    const uint32_t aLo32 = smem_u32(aLoP);
    const uint32_t bHi32 = smem_u32(bHiP);
    const uint32_t bLo32 = smem_u32(bLoP);

    const int tid  = threadIdx.x;
    const int lane = tid & 31;
    const int wid  = tid >> 5;
    const int wm   = wid >> 1;            // 0..3
    const int wn   = wid & 1;             // 0..1
    const int bm   = blockIdx.x * 128;

    // ---- stage + split A tile (128 x K) into smem hi/lo ----
    const int vpr = K >> 2;               // float4 per row
    for (int idx = tid; idx < 128 * vpr; idx += 256) {
        int row = idx / vpr;
        int kq  = (idx - row * vpr) << 2;
        int gm  = bm + row;
        float4 v = make_float4(0.f, 0.f, 0.f, 0.f);
        if (gm < M)
            v = *reinterpret_cast<const float4*>(A + (size_t)gm * lda + kq);
        float f[4] = {v.x, v.y, v.z, v.w};
        uint32_t hw[2], lw[2];
#pragma unroll
        for (int j = 0; j < 2; ++j) {
            __nv_bfloat16 h0 = __float2bfloat16(f[2*j]);
            __nv_bfloat16 h1 = __float2bfloat16(f[2*j+1]);
            __nv_bfloat16 l0 = __float2bfloat16(f[2*j]   - __bfloat162float(h0));
            __nv_bfloat16 l1 = __float2bfloat16(f[2*j+1] - __bfloat162float(h1));
            hw[j] = (uint32_t)__bfloat16_as_ushort(h0) | ((uint32_t)__bfloat16_as_ushort(h1) << 16);
            lw[j] = (uint32_t)__bfloat16_as_ushort(l0) | ((uint32_t)__bfloat16_as_ushort(l1) << 16);
        }
        int off = row * (int)rowB + kq * 2;
        *reinterpret_cast<uint2*>(aHiP + off) = make_uint2(hw[0], hw[1]);
        *reinterpret_cast<uint2*>(aLoP + off) = make_uint2(lw[0], lw[1]);
    }

    // ldmatrix lane addressing: lane&15 -> row-within-16, lane>>4 -> k-half*8
    const uint32_t aOffHi = aHi32 + (uint32_t)((wm * 32 + (lane & 15)) * (int)rowB + (lane >> 4) * 16);
    const uint32_t aOffLo = aLo32 + (uint32_t)((wm * 32 + (lane & 15)) * (int)rowB + (lane >> 4) * 16);
    const uint32_t bOffHi = bHi32 + (uint32_t)((wn * 32 + (lane & 15)) * (int)rowB + (lane >> 4) * 16);
    const uint32_t bOffLo = bLo32 + (uint32_t)((wn * 32 + (lane & 15)) * (int)rowB + (lane >> 4) * 16);

    const bool  act = (alphaPtr != nullptr);
    const float al  = act ? __ldg(alphaPtr) : 1.0f;
    const int   nks = K >> 4;
    const int   u4r = K >> 3;             // uint4 per smem-staged B row

    for (int nb = 0; nb < Ntot; nb += 64) {
        __syncthreads();                  // A ready / previous chunk consumed

        // ---- stage B chunk (64 x K, hi+lo) coalesced from global ----
        for (int idx = tid; idx < 64 * u4r; idx += 256) {
            int n = idx / u4r;
            int q = idx - n * u4r;
            const uint4* sh = reinterpret_cast<const uint4*>(Whi + (size_t)(nb + n) * K) + q;
            const uint4* sl = reinterpret_cast<const uint4*>(Wlo + (size_t)(nb + n) * K) + q;
            *reinterpret_cast<uint4*>(bHiP + n * (int)rowB + q * 16) = *sh;
            *reinterpret_cast<uint4*>(bLoP + n * (int)rowB + q * 16) = *sl;
        }
        __syncthreads();

        float c[2][4][4];
#pragma unroll
        for (int i = 0; i < 2; ++i)
#pragma unroll
            for (int j = 0; j < 4; ++j)
#pragma unroll
                for (int q = 0; q < 4; ++q) c[i][j][q] = 0.f;

        for (int ks = 0; ks < nks; ++ks) {
            const uint32_t kb = (uint32_t)(ks * 32);   // 16 bf16 = 32 bytes

            uint32_t ah0[4], ah1[4], al0[4], al1[4];
            ldsm_x4(ah0[0], ah0[1], ah0[2], ah0[3], aOffHi + kb);
            ldsm_x4(ah1[0], ah1[1], ah1[2], ah1[3], aOffHi + 16 * rowB + kb);
            ldsm_x4(al0[0], al0[1], al0[2], al0[3], aOffLo + kb);
            ldsm_x4(al1[0], al1[1], al1[2], al1[3], aOffLo + 16 * rowB + kb);

            uint32_t s0[4], s1[4], t0[4], t1[4];
            ldsm_x4(s0[0], s0[1], s0[2], s0[3], bOffHi + kb);              // n tiles 0,1
            ldsm_x4(s1[0], s1[1], s1[2], s1[3], bOffHi + 16 * rowB + kb);  // n tiles 2,3
            ldsm_x4(t0[0], t0[1], t0[2], t0[3], bOffLo + kb);
            ldsm_x4(t1[0], t1[1], t1[2], t1[3], bOffLo + 16 * rowB + kb);

            uint32_t bh[4][2] = {{s0[0], s0[2]}, {s0[1], s0[3]},
                                 {s1[0], s1[2]}, {s1[1], s1[3]}};
            uint32_t bl[4][2] = {{t0[0], t0[2]}, {t0[1], t0[3]},
                                 {t1[0], t1[2]}, {t1[1], t1[3]}};
#pragma unroll
            for (int f = 0; f < 4; ++f) {
                mma_bf16(c[0][f], ah0, bh[f]);
                mma_bf16(c[1][f], ah1, bh[f]);
            }
#pragma unroll
            for (int f = 0; f < 4; ++f) {
                mma_bf16(c[0][f], ah0, bl[f]);
                mma_bf16(c[1][f], ah1, bl[f]);
            }
#pragma unroll
            for (int f = 0; f < 4; ++f) {
                mma_bf16(c[0][f], al0, bh[f]);
                mma_bf16(c[1][f], al1, bh[f]);
            }
        }

        // ---- epilogue: bias + leaky-relu, float2 stores ----
#pragma unroll
        for (int f = 0; f < 4; ++f) {
            int col = nb + wn * 32 + f * 8 + (lane & 3) * 2;
            float bx = __ldg(bias + col);
            float by = __ldg(bias + col + 1);
#pragma unroll
            for (int mt = 0; mt < 2; ++mt) {
                int row0 = bm + wm * 32 + mt * 16 + (lane >> 2);
                float v0 = c[mt][f][0] + bx;
                float v1 = c[mt][f][1] + by;
                float v2 = c[mt][f][2] + bx;
                float v3 = c[mt][f][3] + by;
                if (act) {
                    v0 = (v0 >= 0.f) ? v0 : al * v0;
                    v1 = (v1 >= 0.f) ? v1 : al * v1;
                    v2 = (v2 >= 0.f) ? v2 : al * v2;
                    v3 = (v3 >= 0.f) ? v3 : al * v3;
                }
                if (row0 < M)
                    *reinterpret_cast<float2*>(C + (size_t)row0 * ldc + col) =
                        make_float2(v0, v1);
                if (row0 + 8 < M)
                    *reinterpret_cast<float2*>(C + (size_t)(row0 + 8) * ldc + col) =
                        make_float2(v2, v3);
            }
        }
    }
}

// -------------------- node aggregation (segment-sum via atomics) ------------
__global__ void k_scatter() {
    int t = blockIdx.x * blockDim.x + threadIdx.x;
    if (t >= N_EDGES * IN_F) return;
    int e = t >> 6;
    int f = t & 63;
    int r = g_row[e];
    int c = g_col[e];

    float vnr = g_Xr[(size_t)c * HDIM + f];
    float vni = g_Xi[(size_t)c * HDIM + f];
    float ver = g_Yr[(size_t)e * HDIM + f];
    float vei = g_Yi[(size_t)e * HDIM + f];

    atomicAdd(&g_Xr[(size_t)r * HDIM + 64  + f], vnr);
    atomicAdd(&g_Xr[(size_t)r * HDIM + 128 + f], ver);
    atomicAdd(&g_Xi[(size_t)r * HDIM + 64  + f], vni);
    atomicAdd(&g_Xi[(size_t)r * HDIM + 128 + f], vei);
}

// -------------------- edge gather -------------------------------------------
__global__ void k_gather(const float* __restrict__ hr,
                         const float* __restrict__ hi) {
    int t = blockIdx.x * blockDim.x + threadIdx.x;
    if (t >= N_EDGES * IN_F) return;
    int e = t >> 6;
    int f = t & 63;
    int r = g_row[e];
    int c = g_col[e];
    g_Yr[(size_t)e * HDIM + 64  + f] = hr[(size_t)r * OUT_F + f];
    g_Yr[(size_t)e * HDIM + 128 + f] = hr[(size_t)c * OUT_F + f];
    g_Yi[(size_t)e * HDIM + 64  + f] = hi[(size_t)r * OUT_F + f];
    g_Yi[(size_t)e * HDIM + 128 + f] = hi[(size_t)c * OUT_F + f];
}

// ---------------------------------------------------------------------------
static float* symaddr(const void* sym) {
    void* p = nullptr;
    cudaGetSymbolAddress(&p, sym);
    return (float*)p;
}

static __nv_bfloat16* symaddr_bf(const void* sym) {
    void* p = nullptr;
    cudaGetSymbolAddress(&p, sym);
    return (__nv_bfloat16*)p;
}

static inline int smem_bytes_for(int K) {
    return (2 * 128 + 2 * 64) * (K + 8) * 2;
}

static inline void launch_gemm(const float* A, int M, int K, int lda,
                               const __nv_bfloat16* Whi, const __nv_bfloat16* Wlo,
                               int Ntot, const float* bias, const float* alpha,
                               float* C, int ldc) {
    dim3 grid((M + 127) / 128);
    k_gemm_hmma<<<grid, 256, smem_bytes_for(K)>>>(A, M, K, lda, Whi, Wlo, Ntot,
                                                  bias, alpha, C, ldc);
}

extern "C" void kernel_launch(void* const* d_in, const int* in_sizes, int n_in,
                              void* d_out, int out_size)
{
    const float* node_real = (const float*)d_in[0];
    const float* node_imag = (const float*)d_in[1];
    const float* edge_real = (const float*)d_in[2];
    const float* edge_imag = (const float*)d_in[3];
    const void*  edge_idx  = d_in[4];
    const float* Wn        = (const float*)d_in[5];
    const float* bn_       = (const float*)d_in[6];
    const float* We        = (const float*)d_in[7];
    const float* be_       = (const float*)d_in[8];
    const float* node_W    = (const float*)d_in[9];
    const float* node_b    = (const float*)d_in[10];
    const float* node_al   = (const float*)d_in[11];
    const float* node_oW   = (const float*)d_in[12];
    const float* node_ob   = (const float*)d_in[13];
    const float* edge_W    = (const float*)d_in[14];
    const float* edge_b    = (const float*)d_in[15];
    const float* edge_al   = (const float*)d_in[16];
    const float* edge_oW   = (const float*)d_in[17];
    const float* edge_ob   = (const float*)d_in[18];

    float* out  = (float*)d_out;
    float* hr   = out;
    float* hi   = out + (size_t)N_NODES * OUT_F;
    float* outr = out + 2 * (size_t)N_NODES * OUT_F;
    float* outi = outr + (size_t)N_EDGES * OUT_F;

    float* Xr = symaddr(g_Xr);
    float* Xi = symaddr(g_Xi);
    float* Xt = symaddr(g_Xt);
    float* Yr = symaddr(g_Yr);
    float* Yi = symaddr(g_Yi);
    float* Yt = symaddr(g_Yt);
    __nv_bfloat16* Whi = symaddr_bf(g_Whi);
    __nv_bfloat16* Wlo = symaddr_bf(g_Wlo);

    // 154KB dynamic smem for K=192 (idempotent host-side attribute)
    cudaFuncSetAttribute(k_gemm_hmma, cudaFuncAttributeMaxDynamicSharedMemorySize,
                         smem_bytes_for(HDIM));

    const int TPB = 256;

    // 1. edge index conversion
    k_detect<<<1, 32>>>((const unsigned int*)edge_idx);
    k_convert<<<(N_EDGES + TPB - 1) / TPB, TPB>>>(edge_idx);

    // 2. weight splits (fp32 -> bf16 hi/lo)
    k_splitw<<<(4096   + TPB - 1) / TPB, TPB>>>(Wn,      4096,   OFF_WN);
    k_splitw<<<(4096   + TPB - 1) / TPB, TPB>>>(We,      4096,   OFF_WE);
    k_splitw<<<(110592 + TPB - 1) / TPB, TPB>>>(node_W,  110592, OFF_NW);
    k_splitw<<<(12288  + TPB - 1) / TPB, TPB>>>(node_oW, 12288,  OFF_NOW);
    k_splitw<<<(110592 + TPB - 1) / TPB, TPB>>>(edge_W,  110592, OFF_EW);
    k_splitw<<<(12288  + TPB - 1) / TPB, TPB>>>(edge_oW, 12288,  OFF_EOW);

    // 3. zero node agg buffers
    k_zeroX<<<(N_NODES * HDIM + TPB - 1) / TPB, TPB>>>();

    // 4. projections
    launch_gemm(node_real, N_NODES, IN_F, IN_F, Whi + OFF_WN, Wlo + OFF_WN, OUT_F, bn_, nullptr, Xr, HDIM);
    launch_gemm(node_imag, N_NODES, IN_F, IN_F, Whi + OFF_WN, Wlo + OFF_WN, OUT_F, bn_, nullptr, Xi, HDIM);
    launch_gemm(edge_real, N_EDGES, IN_F, IN_F, Whi + OFF_WE, Wlo + OFF_WE, OUT_F, be_, nullptr, Yr, HDIM);
    launch_gemm(edge_imag, N_EDGES, IN_F, IN_F, Whi + OFF_WE, Wlo + OFF_WE, OUT_F, be_, nullptr, Yi, HDIM);

    // 5. node aggregation
    k_scatter<<<(N_EDGES * IN_F + TPB - 1) / TPB, TPB>>>();

    const int HH = HDIM * HDIM;

    // 6. node MLP (real): Xr -> Xt -> Xr -> Xt -> hr
    launch_gemm(Xr, N_NODES, HDIM, HDIM, Whi + OFF_NW,        Wlo + OFF_NW,        HDIM, node_b,          node_al,     Xt, HDIM);
    launch_gemm(Xt, N_NODES, HDIM, HDIM, Whi + OFF_NW + HH,   Wlo + OFF_NW + HH,   HDIM, node_b + HDIM,   node_al + 1, Xr, HDIM);
    launch_gemm(Xr, N_NODES, HDIM, HDIM, Whi + OFF_NW + 2*HH, Wlo + OFF_NW + 2*HH, HDIM, node_b + 2*HDIM, node_al + 2, Xt, HDIM);
    launch_gemm(Xt, N_NODES, HDIM, HDIM, Whi + OFF_NOW,       Wlo + OFF_NOW,       OUT_F, node_ob, nullptr, hr, OUT_F);

    //    node MLP (imag)
    launch_gemm(Xi, N_NODES, HDIM, HDIM, Whi + OFF_NW,        Wlo + OFF_NW,        HDIM, node_b,          node_al,     Xt, HDIM);
    launch_gemm(Xt, N_NODES, HDIM, HDIM, Whi + OFF_NW + HH,   Wlo + OFF_NW + HH,   HDIM, node_b + HDIM,   node_al + 1, Xi, HDIM);
    launch_gemm(Xi, N_NODES, HDIM, HDIM, Whi + OFF_NW + 2*HH, Wlo + OFF_NW + 2*HH, HDIM, node_b + 2*HDIM, node_al + 2, Xt, HDIM);
    launch_gemm(Xt, N_NODES, HDIM, HDIM, Whi + OFF_NOW,       Wlo + OFF_NOW,       OUT_F, node_ob, nullptr, hi, OUT_F);

    // 7. edge gather (needs hr/hi from d_out)
    k_gather<<<(N_EDGES * IN_F + TPB - 1) / TPB, TPB>>>(hr, hi);

    // 8. edge MLP (real)
    launch_gemm(Yr, N_EDGES, HDIM, HDIM, Whi + OFF_EW,        Wlo + OFF_EW,        HDIM, edge_b,          edge_al,     Yt, HDIM);
    launch_gemm(Yt, N_EDGES, HDIM, HDIM, Whi + OFF_EW + HH,   Wlo + OFF_EW + HH,   HDIM, edge_b + HDIM,   edge_al + 1, Yr, HDIM);
    launch_gemm(Yr, N_EDGES, HDIM, HDIM, Whi + OFF_EW + 2*HH, Wlo + OFF_EW + 2*HH, HDIM, edge_b + 2*HDIM, edge_al + 2, Yt, HDIM);
    launch_gemm(Yt, N_EDGES, HDIM, HDIM, Whi + OFF_EOW,       Wlo + OFF_EOW,       OUT_F, edge_ob, nullptr, outr, OUT_F);

    //    edge MLP (imag)
    launch_gemm(Yi, N_EDGES, HDIM, HDIM, Whi + OFF_EW,        Wlo + OFF_EW,        HDIM, edge_b,          edge_al,     Yt, HDIM);
    launch_gemm(Yt, N_EDGES, HDIM, HDIM, Whi + OFF_EW + HH,   Wlo + OFF_EW + HH,   HDIM, edge_b + HDIM,   edge_al + 1, Yi, HDIM);
    launch_gemm(Yi, N_EDGES, HDIM, HDIM, Whi + OFF_EW + 2*HH, Wlo + OFF_EW + 2*HH, HDIM, edge_b + 2*HDIM, edge_al + 2, Yt, HDIM);
    launch_gemm(Yt, N_EDGES, HDIM, HDIM, Whi + OFF_EOW,       Wlo + OFF_EOW,       OUT_F, edge_ob, nullptr, outi, OUT_F);
}

// round 8
// speedup vs baseline: 2.1255x; 1.5022x over previous
#include <cuda_runtime.h>
#include <cuda_bf16.h>
#include <cstdint>

// ---------------------------------------------------------------------------
// MPEdgeNodeBlock — TF32 mma.sync version (single pass, cvt.rna, fp32 accum).
// R5 was 1 CTA/SM (154KB smem) + 3-pass bf16.  R6: M=64 tiles, 100KB smem
// -> 2 CTAs/SM, 1.5x fewer MMAs, no weight-split prepass.
// ---------------------------------------------------------------------------
#define N_NODES 25000
#define N_EDGES 200000
#define IN_F    64
#define OUT_F   64
#define HDIM    192

// -------------------- scratch (device globals; no runtime alloc) ------------
__device__ float g_Xr[N_NODES * HDIM];
__device__ float g_Xi[N_NODES * HDIM];
__device__ float g_Xt[N_NODES * HDIM];
__device__ float g_Yr[(size_t)N_EDGES * HDIM];
__device__ float g_Yi[(size_t)N_EDGES * HDIM];
__device__ float g_Yt[(size_t)N_EDGES * HDIM];
__device__ int   g_row[N_EDGES];
__device__ int   g_col[N_EDGES];
__device__ int   g_is64;

// -------------------- helpers ------------------------------------------------
__device__ __forceinline__ uint32_t smem_u32(const void* p) {
    uint32_t a;
    asm("{ .reg .u64 t; cvta.to.shared.u64 t, %1; cvt.u32.u64 %0, t; }"
        : "=r"(a) : "l"(p));
    return a;
}

__device__ __forceinline__ uint32_t f2tf32(float f) {
    uint32_t r;
    asm("cvt.rna.tf32.f32 %0, %1;" : "=r"(r) : "f"(f));
    return r;
}

__device__ __forceinline__ void ldsm_x4(uint32_t& r0, uint32_t& r1,
                                        uint32_t& r2, uint32_t& r3,
                                        uint32_t addr) {
    asm volatile("ldmatrix.sync.aligned.m8n8.x4.shared.b16 {%0,%1,%2,%3}, [%4];"
                 : "=r"(r0), "=r"(r1), "=r"(r2), "=r"(r3) : "r"(addr));
}

__device__ __forceinline__ void mma_tf32(float* c, const uint32_t* a,
                                         const uint32_t* b) {
    asm volatile(
        "mma.sync.aligned.m16n8k8.row.col.f32.tf32.tf32.f32 "
        "{%0,%1,%2,%3}, {%4,%5,%6,%7}, {%8,%9}, {%0,%1,%2,%3};"
        : "+f"(c[0]), "+f"(c[1]), "+f"(c[2]), "+f"(c[3])
        : "r"(a[0]), "r"(a[1]), "r"(a[2]), "r"(a[3]), "r"(b[0]), "r"(b[1]));
}

// -------------------- edge_index dtype detection + conversion ---------------
__global__ void k_detect(const unsigned int* __restrict__ p) {
    if (threadIdx.x == 0) {
        int all_zero = 1;
        for (int i = 0; i < 128; ++i)
            if (p[2 * i + 1] != 0u) { all_zero = 0; break; }
        g_is64 = all_zero;
    }
}

__global__ void k_convert(const void* __restrict__ raw) {
    int e = blockIdx.x * blockDim.x + threadIdx.x;
    if (e >= N_EDGES) return;
    if (g_is64) {
        const long long* p = (const long long*)raw;
        g_row[e] = (int)p[2 * e];
        g_col[e] = (int)p[2 * e + 1];
    } else {
        const int* p = (const int*)raw;
        g_row[e] = p[2 * e];
        g_col[e] = p[2 * e + 1];
    }
}

__global__ void k_zeroX() {
    int i = blockIdx.x * blockDim.x + threadIdx.x;
    if (i < N_NODES * HDIM) { g_Xr[i] = 0.f; g_Xi[i] = 0.f; }
}

// -------------------- TF32 GEMM: C = act(A @ W^T + b) -----------------------
// A: M x K fp32 (row-major, lda).  W: Ntot x K fp32 row-major.
// Block = 64 rows; 256 threads = 8 warps (2m x 4n); warp tile 32m x 16n.
// Loops n in 64-chunks.  Operands staged in smem as tf32 (cvt.rna), fed by
// ldmatrix.b16 (bit-mover) with the tf32 fragment address trick.
__global__ __launch_bounds__(256)
void k_gemm_tf32(const float* __restrict__ A, int M, int K, int lda,
                 const float* __restrict__ W, int Ntot,
                 const float* __restrict__ bias,
                 const float* __restrict__ alphaPtr,
                 float* __restrict__ C, int ldc)
{
    extern __shared__ __align__(128) char smem[];
    const int KPAD = K + 4;                       // ≡4 (mod 32) -> conflict-free
    float* As = reinterpret_cast<float*>(smem);
    float* Bs = As + 64 * KPAD;
    const uint32_t As32 = smem_u32(As);
    const uint32_t Bs32 = smem_u32(Bs);

    const int tid  = threadIdx.x;
    const int lane = tid & 31;
    const int wid  = tid >> 5;
    const int wm   = wid >> 2;                    // 0..1
    const int wn   = wid & 3;                     // 0..3
    const int bm   = blockIdx.x * 64;

    // ---- stage A tile (64 x K) as tf32 ----
    const int vpr = K >> 2;                       // float4 per row
    for (int idx = tid; idx < 64 * vpr; idx += 256) {
        int row = idx / vpr;
        int c4  = (idx - row * vpr) << 2;
        int gm  = bm + row;
        float4 v = make_float4(0.f, 0.f, 0.f, 0.f);
        if (gm < M)
            v = *reinterpret_cast<const float4*>(A + (size_t)gm * lda + c4);
        uint4 t = make_uint4(f2tf32(v.x), f2tf32(v.y), f2tf32(v.z), f2tf32(v.w));
        *reinterpret_cast<uint4*>(As + row * KPAD + c4) = t;
    }

    // ldmatrix lane addresses
    //  A: lanes 0-15 -> rows (lane&15), col base; lanes 16-31 -> same rows, col+4
    const uint32_t aAddr = As32 +
        (uint32_t)(((wm * 32 + (lane & 15)) * KPAD + (lane >> 4) * 4) * 4);
    //  B: n-row = (lane&7) + ((lane>>4)&1)*8 ; col4 = ((lane>>3)&1)*4
    const int nOff = (lane & 7) + ((lane >> 4) & 1) * 8;
    const uint32_t bAddr = Bs32 +
        (uint32_t)(((wn * 16 + nOff) * KPAD + ((lane >> 3) & 1) * 4) * 4);

    const bool  act = (alphaPtr != nullptr);
    const float al  = act ? __ldg(alphaPtr) : 1.0f;
    const int   nks = K >> 3;
    const uint32_t rowB16 = (uint32_t)(16 * KPAD * 4);

    for (int nb = 0; nb < Ntot; nb += 64) {
        __syncthreads();                          // Bs free / A ready

        // ---- stage B chunk (64 x K) as tf32, coalesced ----
        for (int idx = tid; idx < 64 * vpr; idx += 256) {
            int n  = idx / vpr;
            int c4 = (idx - n * vpr) << 2;
            float4 v = *reinterpret_cast<const float4*>(
                W + (size_t)(nb + n) * K + c4);
            uint4 t = make_uint4(f2tf32(v.x), f2tf32(v.y), f2tf32(v.z), f2tf32(v.w));
            *reinterpret_cast<uint4*>(Bs + n * KPAD + c4) = t;
        }
        __syncthreads();

        float c[2][2][4];
#pragma unroll
        for (int i = 0; i < 2; ++i)
#pragma unroll
            for (int j = 0; j < 2; ++j)
#pragma unroll
                for (int q = 0; q < 4; ++q) c[i][j][q] = 0.f;

        for (int ks = 0; ks < nks; ++ks) {
            const uint32_t kb = (uint32_t)(ks * 32);      // 8 floats = 32 B

            uint32_t a0[4], a1[4], b[4];
            ldsm_x4(a0[0], a0[1], a0[2], a0[3], aAddr + kb);            // rows wm*32..+15
            ldsm_x4(a1[0], a1[1], a1[2], a1[3], aAddr + rowB16 + kb);   // rows +16
            ldsm_x4(b[0],  b[1],  b[2],  b[3],  bAddr + kb);            // 2 n-tiles

            mma_tf32(c[0][0], a0, b);
            mma_tf32(c[0][1], a0, b + 2);
            mma_tf32(c[1][0], a1, b);
            mma_tf32(c[1][1], a1, b + 2);
        }

        // ---- epilogue: bias + leaky-relu, float2 stores ----
#pragma unroll
        for (int nt = 0; nt < 2; ++nt) {
            int col = nb + wn * 16 + nt * 8 + (lane & 3) * 2;
            float bx = __ldg(bias + col);
            float by = __ldg(bias + col + 1);
#pragma unroll
            for (int mt = 0; mt < 2; ++mt) {
                int row0 = bm + wm * 32 + mt * 16 + (lane >> 2);
                float v0 = c[mt][nt][0] + bx;
                float v1 = c[mt][nt][1] + by;
                float v2 = c[mt][nt][2] + bx;
                float v3 = c[mt][nt][3] + by;
                if (act) {
                    v0 = (v0 >= 0.f) ? v0 : al * v0;
                    v1 = (v1 >= 0.f) ? v1 : al * v1;
                    v2 = (v2 >= 0.f) ? v2 : al * v2;
                    v3 = (v3 >= 0.f) ? v3 : al * v3;
                }
                if (row0 < M)
                    *reinterpret_cast<float2*>(C + (size_t)row0 * ldc + col) =
                        make_float2(v0, v1);
                if (row0 + 8 < M)
                    *reinterpret_cast<float2*>(C + (size_t)(row0 + 8) * ldc + col) =
                        make_float2(v2, v3);
            }
        }
    }
}

// -------------------- node aggregation (segment-sum via atomics) ------------
__global__ void k_scatter() {
    int t = blockIdx.x * blockDim.x + threadIdx.x;
    if (t >= N_EDGES * IN_F) return;
    int e = t >> 6;
    int f = t & 63;
    int r = g_row[e];
    int c = g_col[e];

    float vnr = g_Xr[(size_t)c * HDIM + f];
    float vni = g_Xi[(size_t)c * HDIM + f];
    float ver = g_Yr[(size_t)e * HDIM + f];
    float vei = g_Yi[(size_t)e * HDIM + f];

    atomicAdd(&g_Xr[(size_t)r * HDIM + 64  + f], vnr);
    atomicAdd(&g_Xr[(size_t)r * HDIM + 128 + f], ver);
    atomicAdd(&g_Xi[(size_t)r * HDIM + 64  + f], vni);
    atomicAdd(&g_Xi[(size_t)r * HDIM + 128 + f], vei);
}

// -------------------- edge gather -------------------------------------------
__global__ void k_gather(const float* __restrict__ hr,
                         const float* __restrict__ hi) {
    int t = blockIdx.x * blockDim.x + threadIdx.x;
    if (t >= N_EDGES * IN_F) return;
    int e = t >> 6;
    int f = t & 63;
    int r = g_row[e];
    int c = g_col[e];
    g_Yr[(size_t)e * HDIM + 64  + f] = hr[(size_t)r * OUT_F + f];
    g_Yr[(size_t)e * HDIM + 128 + f] = hr[(size_t)c * OUT_F + f];
    g_Yi[(size_t)e * HDIM + 64  + f] = hi[(size_t)r * OUT_F + f];
    g_Yi[(size_t)e * HDIM + 128 + f] = hi[(size_t)c * OUT_F + f];
}

// ---------------------------------------------------------------------------
static float* symaddr(const void* sym) {
    void* p = nullptr;
    cudaGetSymbolAddress(&p, sym);
    return (float*)p;
}

static inline int smem_bytes_for(int K) {
    return 128 * (K + 4) * 4;     // (64 A rows + 64 B rows) * KPAD * 4B
}

static inline void launch_gemm(const float* A, int M, int K, int lda,
                               const float* W, int Ntot,
                               const float* bias, const float* alpha,
                               float* C, int ldc) {
    dim3 grid((M + 63) / 64);
    k_gemm_tf32<<<grid, 256, smem_bytes_for(K)>>>(A, M, K, lda, W, Ntot,
                                                  bias, alpha, C, ldc);
}

extern "C" void kernel_launch(void* const* d_in, const int* in_sizes, int n_in,
                              void* d_out, int out_size)
{
    const float* node_real = (const float*)d_in[0];
    const float* node_imag = (const float*)d_in[1];
    const float* edge_real = (const float*)d_in[2];
    const float* edge_imag = (const float*)d_in[3];
    const void*  edge_idx  = d_in[4];
    const float* Wn        = (const float*)d_in[5];
    const float* bn_       = (const float*)d_in[6];
    const float* We        = (const float*)d_in[7];
    const float* be_       = (const float*)d_in[8];
    const float* node_W    = (const float*)d_in[9];
    const float* node_b    = (const float*)d_in[10];
    const float* node_al   = (const float*)d_in[11];
    const float* node_oW   = (const float*)d_in[12];
    const float* node_ob   = (const float*)d_in[13];
    const float* edge_W    = (const float*)d_in[14];
    const float* edge_b    = (const float*)d_in[15];
    const float* edge_al   = (const float*)d_in[16];
    const float* edge_oW   = (const float*)d_in[17];
    const float* edge_ob   = (const float*)d_in[18];

    float* out  = (float*)d_out;
    float* hr   = out;
    float* hi   = out + (size_t)N_NODES * OUT_F;
    float* outr = out + 2 * (size_t)N_NODES * OUT_F;
    float* outi = outr + (size_t)N_EDGES * OUT_F;

    float* Xr = symaddr(g_Xr);
    float* Xi = symaddr(g_Xi);
    float* Xt = symaddr(g_Xt);
    float* Yr = symaddr(g_Yr);
    float* Yi = symaddr(g_Yi);
    float* Yt = symaddr(g_Yt);

    // opt in to 100KB dynamic smem (idempotent host-side attribute)
    cudaFuncSetAttribute(k_gemm_tf32, cudaFuncAttributeMaxDynamicSharedMemorySize,
                         smem_bytes_for(HDIM));

    const int TPB = 256;

    // 1. edge index conversion + zero agg buffers   (launches 1-3)
    k_detect<<<1, 32>>>((const unsigned int*)edge_idx);
    k_convert<<<(N_EDGES + TPB - 1) / TPB, TPB>>>(edge_idx);
    k_zeroX<<<(N_NODES * HDIM + TPB - 1) / TPB, TPB>>>();

    // 2. projections (launches 4-7; ncu -s 5 profiles #6 = edge_real proj)
    launch_gemm(node_real, N_NODES, IN_F, IN_F, Wn, OUT_F, bn_, nullptr, Xr, HDIM);
    launch_gemm(node_imag, N_NODES, IN_F, IN_F, Wn, OUT_F, bn_, nullptr, Xi, HDIM);
    launch_gemm(edge_real, N_EDGES, IN_F, IN_F, We, OUT_F, be_, nullptr, Yr, HDIM);
    launch_gemm(edge_imag, N_EDGES, IN_F, IN_F, We, OUT_F, be_, nullptr, Yi, HDIM);

    // 3. node aggregation
    k_scatter<<<(N_EDGES * IN_F + TPB - 1) / TPB, TPB>>>();

    const int HH = HDIM * HDIM;

    // 4. node MLP (real): Xr -> Xt -> Xr -> Xt -> hr
    launch_gemm(Xr, N_NODES, HDIM, HDIM, node_W,          HDIM, node_b,          node_al,     Xt, HDIM);
    launch_gemm(Xt, N_NODES, HDIM, HDIM, node_W + HH,     HDIM, node_b + HDIM,   node_al + 1, Xr, HDIM);
    launch_gemm(Xr, N_NODES, HDIM, HDIM, node_W + 2*HH,   HDIM, node_b + 2*HDIM, node_al + 2, Xt, HDIM);
    launch_gemm(Xt, N_NODES, HDIM, HDIM, node_oW,         OUT_F, node_ob, nullptr, hr, OUT_F);

    //    node MLP (imag)
    launch_gemm(Xi, N_NODES, HDIM, HDIM, node_W,          HDIM, node_b,          node_al,     Xt, HDIM);
    launch_gemm(Xt, N_NODES, HDIM, HDIM, node_W + HH,     HDIM, node_b + HDIM,   node_al + 1, Xi, HDIM);
    launch_gemm(Xi, N_NODES, HDIM, HDIM, node_W + 2*HH,   HDIM, node_b + 2*HDIM, node_al + 2, Xt, HDIM);
    launch_gemm(Xt, N_NODES, HDIM, HDIM, node_oW,         OUT_F, node_ob, nullptr, hi, OUT_F);

    // 5. edge gather (needs hr/hi from d_out)
    k_gather<<<(N_EDGES * IN_F + TPB - 1) / TPB, TPB>>>(hr, hi);

    // 6. edge MLP (real)
    launch_gemm(Yr, N_EDGES, HDIM, HDIM, edge_W,          HDIM, edge_b,          edge_al,     Yt, HDIM);
    launch_gemm(Yt, N_EDGES, HDIM, HDIM, edge_W + HH,     HDIM, edge_b + HDIM,   edge_al + 1, Yr, HDIM);
    launch_gemm(Yr, N_EDGES, HDIM, HDIM, edge_W + 2*HH,   HDIM, edge_b + 2*HDIM, edge_al + 2, Yt, HDIM);
    launch_gemm(Yt, N_EDGES, HDIM, HDIM, edge_oW,         OUT_F, edge_ob, nullptr, outr, OUT_F);

    //    edge MLP (imag)
    launch_gemm(Yi, N_EDGES, HDIM, HDIM, edge_W,          HDIM, edge_b,          edge_al,     Yt, HDIM);
    launch_gemm(Yt, N_EDGES, HDIM, HDIM, edge_W + HH,     HDIM, edge_b + HDIM,   edge_al + 1, Yi, HDIM);
    launch_gemm(Yi, N_EDGES, HDIM, HDIM, edge_W + 2*HH,   HDIM, edge_b + 2*HDIM, edge_al + 2, Yt, HDIM);
    launch_gemm(Yt, N_EDGES, HDIM, HDIM, edge_oW,         OUT_F, edge_ob, nullptr, outi, OUT_F);
}

// round 10
// speedup vs baseline: 2.5690x; 1.2087x over previous
#include <cuda_runtime.h>
#include <cstdint>

// ---------------------------------------------------------------------------
// MPEdgeNodeBlock — TF32 mma.sync, cp.async staging, pre-rounded operands,
// gather fused into edge-MLP layer-1 staging.
// ---------------------------------------------------------------------------
#define N_NODES  25000
#define NODE_PAD 25024            // 391 * 64, pad so cp.async never reads OOB
#define N_EDGES  200000
#define IN_F     64
#define OUT_F    64
#define HDIM     192

// -------------------- scratch (device globals; no runtime alloc) ------------
__device__ float g_Xr[NODE_PAD * HDIM];
__device__ float g_Xi[NODE_PAD * HDIM];
__device__ float g_Xt[NODE_PAD * HDIM];
__device__ float g_Er[(size_t)N_EDGES * OUT_F];   // compact edge proj (real)
__device__ float g_Ei[(size_t)N_EDGES * OUT_F];
__device__ float g_Yr[(size_t)N_EDGES * HDIM];    // edge MLP ping-pong
__device__ float g_Yi[(size_t)N_EDGES * HDIM];
__device__ float g_Yt[(size_t)N_EDGES * HDIM];
__device__ int   g_row[N_EDGES];
__device__ int   g_col[N_EDGES];
__device__ int   g_is64;
// tf32-pre-rounded weights, concatenated
#define W_TOTAL 253952
__device__ float g_Wt[W_TOTAL];
#define OFF_WN   0
#define OFF_WE   4096
#define OFF_NW   8192
#define OFF_NOW  118784
#define OFF_EW   131072
#define OFF_EOW  241664

// -------------------- helpers ------------------------------------------------
__device__ __forceinline__ uint32_t smem_u32(const void* p) {
    uint32_t a;
    asm("{ .reg .u64 t; cvta.to.shared.u64 t, %1; cvt.u32.u64 %0, t; }"
        : "=r"(a) : "l"(p));
    return a;
}

__device__ __forceinline__ float tf32r(float f) {
    uint32_t r;
    asm("cvt.rna.tf32.f32 %0, %1;" : "=r"(r) : "f"(f));
    return __uint_as_float(r);
}

__device__ __forceinline__ void ldsm_x4(uint32_t& r0, uint32_t& r1,
                                        uint32_t& r2, uint32_t& r3,
                                        uint32_t addr) {
    asm volatile("ldmatrix.sync.aligned.m8n8.x4.shared.b16 {%0,%1,%2,%3}, [%4];"
                 : "=r"(r0), "=r"(r1), "=r"(r2), "=r"(r3) : "r"(addr));
}

__device__ __forceinline__ void mma_tf32(float* c, const uint32_t* a,
                                         const uint32_t* b) {
    asm volatile(
        "mma.sync.aligned.m16n8k8.row.col.f32.tf32.tf32.f32 "
        "{%0,%1,%2,%3}, {%4,%5,%6,%7}, {%8,%9}, {%0,%1,%2,%3};"
        : "+f"(c[0]), "+f"(c[1]), "+f"(c[2]), "+f"(c[3])
        : "r"(a[0]), "r"(a[1]), "r"(a[2]), "r"(a[3]), "r"(b[0]), "r"(b[1]));
}

__device__ __forceinline__ void cp16(uint32_t dst, const void* src) {
    asm volatile("cp.async.cg.shared.global [%0], [%1], 16;"
                 :: "r"(dst), "l"(src));
}

// -------------------- edge_index dtype detection + conversion ---------------
__global__ void k_detect(const unsigned int* __restrict__ p) {
    if (threadIdx.x == 0) {
        int all_zero = 1;
        for (int i = 0; i < 128; ++i)
            if (p[2 * i + 1] != 0u) { all_zero = 0; break; }
        g_is64 = all_zero;
    }
}

__global__ void k_convert(const void* __restrict__ raw) {
    int e = blockIdx.x * blockDim.x + threadIdx.x;
    if (e >= N_EDGES) return;
    if (g_is64) {
        const long long* p = (const long long*)raw;
        g_row[e] = (int)p[2 * e];
        g_col[e] = (int)p[2 * e + 1];
    } else {
        const int* p = (const int*)raw;
        g_row[e] = p[2 * e];
        g_col[e] = p[2 * e + 1];
    }
}

// -------------------- weight prep: round to tf32 once ------------------------
__global__ void k_prepW(const float* s0, const float* s1, const float* s2,
                        const float* s3, const float* s4, const float* s5) {
    const int sizes[6] = {4096, 4096, 110592, 12288, 110592, 12288};
    const int offs[6]  = {OFF_WN, OFF_WE, OFF_NW, OFF_NOW, OFF_EW, OFF_EOW};
    int t = blockIdx.y;
    const float* s = (t == 0) ? s0 : (t == 1) ? s1 : (t == 2) ? s2
                   : (t == 3) ? s3 : (t == 4) ? s4 : s5;
    for (int i = blockIdx.x * blockDim.x + threadIdx.x; i < sizes[t];
         i += gridDim.x * blockDim.x)
        g_Wt[offs[t] + i] = tf32r(s[i]);
}

__global__ void k_zeroX() {
    int i = blockIdx.x * blockDim.x + threadIdx.x;
    if (i < N_NODES * HDIM) { g_Xr[i] = 0.f; g_Xi[i] = 0.f; }
}

// round agg buffers post-scatter so RAW staging consumes exact-tf32 values
__global__ void k_roundX() {
    int i = blockIdx.x * blockDim.x + threadIdx.x;
    if (i < N_NODES * HDIM) {
        g_Xr[i] = tf32r(g_Xr[i]);
        g_Xi[i] = tf32r(g_Xi[i]);
    }
}

// -------------------- TF32 GEMM: C = act(A @ W^T + b) -----------------------
// MODE 0 (CVT):  A raw fp32, LDG+cvt+STS staging.
// MODE 1 (RAW):  A pre-rounded, cp.async staging.
// MODE 2 (GATH): A = concat(E[e,0:64], H[row[e]], H[col[e]]), LDG+cvt+STS.
// Block = 64 rows, 256 thr = 8 warps (2m x 4n), warp tile 32m x 16n.
template <int K, int MODE>
__global__ __launch_bounds__(256)
void k_gemm(const float* __restrict__ A, int M, int lda,
            const float* __restrict__ W, int Ntot,
            const float* __restrict__ bias,
            const float* __restrict__ alphaPtr,
            float* __restrict__ C, int ldc, int roundOut,
            const float* __restrict__ GH)
{
    constexpr int KPAD = K + 4;
    constexpr int vpr  = K / 4;
    extern __shared__ __align__(16) char smem[];
    float* As = reinterpret_cast<float*>(smem);
    float* Bs = As + 64 * KPAD;
    const uint32_t As32 = smem_u32(As);
    const uint32_t Bs32 = smem_u32(Bs);

    const int tid  = threadIdx.x;
    const int lane = tid & 31;
    const int wid  = tid >> 5;
    const int wm   = wid >> 2;
    const int wn   = wid & 3;
    const int bm   = blockIdx.x * 64;

    // ---- stage A tile (64 x K) ----
    if (MODE == 0) {
        for (int idx = tid; idx < 64 * vpr; idx += 256) {
            int row = idx / vpr, c4 = (idx - row * vpr) * 4, gm = bm + row;
            float4 v = make_float4(0.f, 0.f, 0.f, 0.f);
            if (gm < M)
                v = *reinterpret_cast<const float4*>(A + (size_t)gm * lda + c4);
            *reinterpret_cast<float4*>(As + row * KPAD + c4) =
                make_float4(tf32r(v.x), tf32r(v.y), tf32r(v.z), tf32r(v.w));
        }
    } else if (MODE == 1) {
        for (int idx = tid; idx < 64 * vpr; idx += 256) {
            int row = idx / vpr, c4 = (idx - row * vpr) * 4, gm = bm + row;
            cp16(As32 + (uint32_t)((row * KPAD + c4) * 4),
                 A + (size_t)gm * lda + c4);
        }
        asm volatile("cp.async.commit_group;");
    } else {
        for (int idx = tid; idx < 64 * vpr; idx += 256) {
            int row = idx / vpr, c4 = (idx - row * vpr) * 4, e = bm + row;
            int seg = c4 >> 6, off = c4 & 63;
            const float* src;
            if (seg == 0) {
                src = A + (size_t)e * 64 + off;
            } else {
                int n = (seg == 1) ? __ldg(&g_row[e]) : __ldg(&g_col[e]);
                src = GH + (size_t)n * 64 + off;
            }
            float4 v = *reinterpret_cast<const float4*>(src);
            *reinterpret_cast<float4*>(As + row * KPAD + c4) =
                make_float4(tf32r(v.x), tf32r(v.y), tf32r(v.z), tf32r(v.w));
        }
    }

    // ldmatrix lane addresses (validated in R8)
    const uint32_t aAddr = As32 +
        (uint32_t)(((wm * 32 + (lane & 15)) * KPAD + (lane >> 4) * 4) * 4);
    const int nOff = (lane & 7) + ((lane >> 4) & 1) * 8;
    const uint32_t bAddr = Bs32 +
        (uint32_t)(((wn * 16 + nOff) * KPAD + ((lane >> 3) & 1) * 4) * 4);

    const bool  act = (alphaPtr != nullptr);
    const float al  = act ? __ldg(alphaPtr) : 1.0f;
    constexpr uint32_t rowB16 = (uint32_t)(16 * KPAD * 4);

    for (int nb = 0; nb < Ntot; nb += 64) {
        __syncthreads();                       // Bs free / As stores visible

        // ---- stage B chunk (64 x K) via cp.async (pre-rounded W) ----
        for (int idx = tid; idx < 64 * vpr; idx += 256) {
            int n = idx / vpr, c4 = (idx - n * vpr) * 4;
            cp16(Bs32 + (uint32_t)((n * KPAD + c4) * 4),
                 W + (size_t)(nb + n) * K + c4);
        }
        asm volatile("cp.async.commit_group;");
        asm volatile("cp.async.wait_group 0;");
        __syncthreads();

        float c[2][2][4];
#pragma unroll
        for (int i = 0; i < 2; ++i)
#pragma unroll
            for (int j = 0; j < 2; ++j)
#pragma unroll
                for (int q = 0; q < 4; ++q) c[i][j][q] = 0.f;

#pragma unroll
        for (int ks = 0; ks < K / 8; ++ks) {
            const uint32_t kb = (uint32_t)(ks * 32);
            uint32_t a0[4], a1[4], b[4];
            ldsm_x4(a0[0], a0[1], a0[2], a0[3], aAddr + kb);
            ldsm_x4(a1[0], a1[1], a1[2], a1[3], aAddr + rowB16 + kb);
            ldsm_x4(b[0],  b[1],  b[2],  b[3],  bAddr + kb);
            mma_tf32(c[0][0], a0, b);
            mma_tf32(c[0][1], a0, b + 2);
            mma_tf32(c[1][0], a1, b);
            mma_tf32(c[1][1], a1, b + 2);
        }

        // ---- epilogue: bias + leaky-relu (+ tf32 round for intermediates) --
#pragma unroll
        for (int nt = 0; nt < 2; ++nt) {
            int col = nb + wn * 16 + nt * 8 + (lane & 3) * 2;
            float bx = __ldg(bias + col);
            float by = __ldg(bias + col + 1);
#pragma unroll
            for (int mt = 0; mt < 2; ++mt) {
                int row0 = bm + wm * 32 + mt * 16 + (lane >> 2);
                float v0 = c[mt][nt][0] + bx;
                float v1 = c[mt][nt][1] + by;
                float v2 = c[mt][nt][2] + bx;
                float v3 = c[mt][nt][3] + by;
                if (act) {
                    v0 = (v0 >= 0.f) ? v0 : al * v0;
                    v1 = (v1 >= 0.f) ? v1 : al * v1;
                    v2 = (v2 >= 0.f) ? v2 : al * v2;
                    v3 = (v3 >= 0.f) ? v3 : al * v3;
                }
                if (roundOut) {
                    v0 = tf32r(v0); v1 = tf32r(v1);
                    v2 = tf32r(v2); v3 = tf32r(v3);
                }
                if (row0 < M)
                    *reinterpret_cast<float2*>(C + (size_t)row0 * ldc + col) =
                        make_float2(v0, v1);
                if (row0 + 8 < M)
                    *reinterpret_cast<float2*>(C + (size_t)(row0 + 8) * ldc + col) =
                        make_float2(v2, v3);
            }
        }
    }
}

// -------------------- node aggregation (segment-sum via atomics) ------------
__global__ void k_scatter() {
    int t = blockIdx.x * blockDim.x + threadIdx.x;
    if (t >= N_EDGES * IN_F) return;
    int e = t >> 6;
    int f = t & 63;
    int r = g_row[e];
    int c = g_col[e];

    float vnr = g_Xr[(size_t)c * HDIM + f];          // nr[col] (cols 0:64)
    float vni = g_Xi[(size_t)c * HDIM + f];
    float ver = g_Er[(size_t)e * 64 + f];            // er[e] (compact)
    float vei = g_Ei[(size_t)e * 64 + f];

    atomicAdd(&g_Xr[(size_t)r * HDIM + 64  + f], vnr);
    atomicAdd(&g_Xr[(size_t)r * HDIM + 128 + f], ver);
    atomicAdd(&g_Xi[(size_t)r * HDIM + 64  + f], vni);
    atomicAdd(&g_Xi[(size_t)r * HDIM + 128 + f], vei);
}

// ---------------------------------------------------------------------------
static float* symaddr(const void* sym) {
    void* p = nullptr;
    cudaGetSymbolAddress(&p, sym);
    return (float*)p;
}

extern "C" void kernel_launch(void* const* d_in, const int* in_sizes, int n_in,
                              void* d_out, int out_size)
{
    const float* node_real = (const float*)d_in[0];
    const float* node_imag = (const float*)d_in[1];
    const float* edge_real = (const float*)d_in[2];
    const float* edge_imag = (const float*)d_in[3];
    const void*  edge_idx  = d_in[4];
    const float* Wn        = (const float*)d_in[5];
    const float* bn_       = (const float*)d_in[6];
    const float* We        = (const float*)d_in[7];
    const float* be_       = (const float*)d_in[8];
    const float* node_W    = (const float*)d_in[9];
    const float* node_b    = (const float*)d_in[10];
    const float* node_al   = (const float*)d_in[11];
    const float* node_oW   = (const float*)d_in[12];
    const float* node_ob   = (const float*)d_in[13];
    const float* edge_W    = (const float*)d_in[14];
    const float* edge_b    = (const float*)d_in[15];
    const float* edge_al   = (const float*)d_in[16];
    const float* edge_oW   = (const float*)d_in[17];
    const float* edge_ob   = (const float*)d_in[18];

    float* out  = (float*)d_out;
    float* hr   = out;
    float* hi   = out + (size_t)N_NODES * OUT_F;
    float* outr = out + 2 * (size_t)N_NODES * OUT_F;
    float* outi = outr + (size_t)N_EDGES * OUT_F;

    float* Xr = symaddr(g_Xr);
    float* Xi = symaddr(g_Xi);
    float* Xt = symaddr(g_Xt);
    float* Er = symaddr(g_Er);
    float* Ei = symaddr(g_Ei);
    float* Yr = symaddr(g_Yr);
    float* Yi = symaddr(g_Yi);
    float* Yt = symaddr(g_Yt);
    float* Wt = symaddr(g_Wt);

    const int SMEM64  = 128 * (64 + 4) * 4;      // 34.8 KB
    const int SMEM192 = 128 * (192 + 4) * 4;     // 100.4 KB
    cudaFuncSetAttribute(k_gemm<64, 0>, cudaFuncAttributeMaxDynamicSharedMemorySize, SMEM64);
    cudaFuncSetAttribute(k_gemm<192, 1>, cudaFuncAttributeMaxDynamicSharedMemorySize, SMEM192);
    cudaFuncSetAttribute(k_gemm<192, 2>, cudaFuncAttributeMaxDynamicSharedMemorySize, SMEM192);

    const int TPB = 256;
    const int gN  = (N_NODES + 63) / 64;   // 391
    const int gE  = N_EDGES / 64;          // 3125

    // 1-2. edge index conversion
    k_detect<<<1, 32>>>((const unsigned int*)edge_idx);
    k_convert<<<(N_EDGES + TPB - 1) / TPB, TPB>>>(edge_idx);

    // 3. weight prep (tf32 round, one kernel)
    k_prepW<<<dim3(432, 6), TPB>>>(Wn, We, node_W, node_oW, edge_W, edge_oW);

    // 4. zero node agg buffers
    k_zeroX<<<(N_NODES * HDIM + TPB - 1) / TPB, TPB>>>();

    // 5-8. projections (CVT path; edge ones first)
    k_gemm<64, 0><<<gE, TPB, SMEM64>>>(edge_real, N_EDGES, IN_F, Wt + OFF_WE, OUT_F, be_, nullptr, Er, OUT_F, 1, nullptr);
    k_gemm<64, 0><<<gE, TPB, SMEM64>>>(edge_imag, N_EDGES, IN_F, Wt + OFF_WE, OUT_F, be_, nullptr, Ei, OUT_F, 1, nullptr);
    k_gemm<64, 0><<<gN, TPB, SMEM64>>>(node_real, N_NODES, IN_F, Wt + OFF_WN, OUT_F, bn_, nullptr, Xr, HDIM, 1, nullptr);
    k_gemm<64, 0><<<gN, TPB, SMEM64>>>(node_imag, N_NODES, IN_F, Wt + OFF_WN, OUT_F, bn_, nullptr, Xi, HDIM, 1, nullptr);

    // 9. node aggregation, 10. round agg to tf32
    k_scatter<<<(N_EDGES * IN_F + TPB - 1) / TPB, TPB>>>();
    k_roundX<<<(N_NODES * HDIM + TPB - 1) / TPB, TPB>>>();

    const int HH = HDIM * HDIM;

    // 11-18. node MLPs (RAW path)
    k_gemm<192, 1><<<gN, TPB, SMEM192>>>(Xr, N_NODES, HDIM, Wt + OFF_NW,        HDIM, node_b,          node_al,     Xt, HDIM, 1, nullptr);
    k_gemm<192, 1><<<gN, TPB, SMEM192>>>(Xt, N_NODES, HDIM, Wt + OFF_NW + HH,   HDIM, node_b + HDIM,   node_al + 1, Xr, HDIM, 1, nullptr);
    k_gemm<192, 1><<<gN, TPB, SMEM192>>>(Xr, N_NODES, HDIM, Wt + OFF_NW + 2*HH, HDIM, node_b + 2*HDIM, node_al + 2, Xt, HDIM, 1, nullptr);
    k_gemm<192, 1><<<gN, TPB, SMEM192>>>(Xt, N_NODES, HDIM, Wt + OFF_NOW,       OUT_F, node_ob, nullptr, hr, OUT_F, 0, nullptr);

    k_gemm<192, 1><<<gN, TPB, SMEM192>>>(Xi, N_NODES, HDIM, Wt + OFF_NW,        HDIM, node_b,          node_al,     Xt, HDIM, 1, nullptr);
    k_gemm<192, 1><<<gN, TPB, SMEM192>>>(Xt, N_NODES, HDIM, Wt + OFF_NW + HH,   HDIM, node_b + HDIM,   node_al + 1, Xi, HDIM, 1, nullptr);
    k_gemm<192, 1><<<gN, TPB, SMEM192>>>(Xi, N_NODES, HDIM, Wt + OFF_NW + 2*HH, HDIM, node_b + 2*HDIM, node_al + 2, Xt, HDIM, 1, nullptr);
    k_gemm<192, 1><<<gN, TPB, SMEM192>>>(Xt, N_NODES, HDIM, Wt + OFF_NOW,       OUT_F, node_ob, nullptr, hi, OUT_F, 0, nullptr);

    // 19-26. edge MLPs; layer 1 gathers hr/hi on the fly (GATH path)
    k_gemm<192, 2><<<gE, TPB, SMEM192>>>(Er, N_EDGES, 64,  Wt + OFF_EW,        HDIM, edge_b,          edge_al,     Yt, HDIM, 1, hr);
    k_gemm<192, 1><<<gE, TPB, SMEM192>>>(Yt, N_EDGES, HDIM, Wt + OFF_EW + HH,   HDIM, edge_b + HDIM,   edge_al + 1, Yr, HDIM, 1, nullptr);
    k_gemm<192, 1><<<gE, TPB, SMEM192>>>(Yr, N_EDGES, HDIM, Wt + OFF_EW + 2*HH, HDIM, edge_b + 2*HDIM, edge_al + 2, Yt, HDIM, 1, nullptr);
    k_gemm<192, 1><<<gE, TPB, SMEM192>>>(Yt, N_EDGES, HDIM, Wt + OFF_EOW,       OUT_F, edge_ob, nullptr, outr, OUT_F, 0, nullptr);

    k_gemm<192, 2><<<gE, TPB, SMEM192>>>(Ei, N_EDGES, 64,  Wt + OFF_EW,        HDIM, edge_b,          edge_al,     Yt, HDIM, 1, hi);
    k_gemm<192, 1><<<gE, TPB, SMEM192>>>(Yt, N_EDGES, HDIM, Wt + OFF_EW + HH,   HDIM, edge_b + HDIM,   edge_al + 1, Yi, HDIM, 1, nullptr);
    k_gemm<192, 1><<<gE, TPB, SMEM192>>>(Yi, N_EDGES, HDIM, Wt + OFF_EW + 2*HH, HDIM, edge_b + 2*HDIM, edge_al + 2, Yt, HDIM, 1, nullptr);
    k_gemm<192, 1><<<gE, TPB, SMEM192>>>(Yt, N_EDGES, HDIM, Wt + OFF_EOW,       OUT_F, edge_ob, nullptr, outi, OUT_F, 0, nullptr);
}